// round 1
// baseline (speedup 1.0000x reference)
#include <cuda_runtime.h>
#include <cuda_bf16.h>

// loss = N(N-1)*DELTA - N*sum_i diag_i + dot(u, v)
//   diag_i = (X_i . Y_i) / max(||X_i|| * ||Y_i||, 1e-8)
//   u = sum_i X_i / ||X_i||,  v = sum_j Y_j / ||Y_j||
//
// Pure O(N*D) streaming: read X and Y exactly once (50 MB), HBM-bound.

#define D_DIM   768
#define THREADS 256           // 3 elements per thread: t, t+256, t+512
#define GRID    592           // ~4 blocks/SM on 148-SM B200
#define DELTA_D 0.2
#define EPS_F   1e-8f

__device__ float g_u[D_DIM];
__device__ float g_v[D_DIM];
__device__ float g_diag;

__global__ void zero_kernel() {
    int t = threadIdx.x;
    for (int d = t; d < D_DIM; d += blockDim.x) {
        g_u[d] = 0.0f;
        g_v[d] = 0.0f;
    }
    if (t == 0) g_diag = 0.0f;
}

__global__ void __launch_bounds__(THREADS)
stream_kernel(const float* __restrict__ X, const float* __restrict__ Y, int nrows) {
    __shared__ float red[3][8];   // per-warp partials: sx, sy, sxy
    __shared__ float bc[2];       // broadcast rxn, ryn

    const int t    = threadIdx.x;
    const int lane = t & 31;
    const int warp = t >> 5;

    float u0 = 0.f, u1 = 0.f, u2 = 0.f;
    float v0 = 0.f, v1 = 0.f, v2 = 0.f;
    float dacc = 0.f;   // only meaningful on thread 0

    for (int row = blockIdx.x; row < nrows; row += gridDim.x) {
        const float* xr = X + (size_t)row * D_DIM;
        const float* yr = Y + (size_t)row * D_DIM;

        float x0 = xr[t], x1 = xr[t + 256], x2 = xr[t + 512];
        float y0 = yr[t], y1 = yr[t + 256], y2 = yr[t + 512];

        float sx  = x0 * x0 + x1 * x1 + x2 * x2;
        float sy  = y0 * y0 + y1 * y1 + y2 * y2;
        float sxy = x0 * y0 + x1 * y1 + x2 * y2;

        #pragma unroll
        for (int o = 16; o > 0; o >>= 1) {
            sx  += __shfl_down_sync(0xffffffffu, sx,  o);
            sy  += __shfl_down_sync(0xffffffffu, sy,  o);
            sxy += __shfl_down_sync(0xffffffffu, sxy, o);
        }
        if (lane == 0) {
            red[0][warp] = sx;
            red[1][warp] = sy;
            red[2][warp] = sxy;
        }
        __syncthreads();

        if (warp == 0) {
            float a = (lane < 8) ? red[0][lane] : 0.f;
            float b = (lane < 8) ? red[1][lane] : 0.f;
            float c = (lane < 8) ? red[2][lane] : 0.f;
            #pragma unroll
            for (int o = 4; o > 0; o >>= 1) {
                a += __shfl_down_sync(0xffffffffu, a, o);
                b += __shfl_down_sync(0xffffffffu, b, o);
                c += __shfl_down_sync(0xffffffffu, c, o);
            }
            if (lane == 0) {
                float rxn = rsqrtf(a);
                float ryn = rsqrtf(b);
                float denom = fmaxf(sqrtf(a) * sqrtf(b), EPS_F);
                dacc += c / denom;
                bc[0] = rxn;
                bc[1] = ryn;
            }
        }
        __syncthreads();

        float rxn = bc[0];
        float ryn = bc[1];
        u0 += x0 * rxn; u1 += x1 * rxn; u2 += x2 * rxn;
        v0 += y0 * ryn; v1 += y1 * ryn; v2 += y2 * ryn;
        // No extra sync needed: next iteration's first __syncthreads orders
        // the red[]/bc[] reuse against this iteration's reads.
    }

    atomicAdd(&g_u[t],       u0);
    atomicAdd(&g_u[t + 256], u1);
    atomicAdd(&g_u[t + 512], u2);
    atomicAdd(&g_v[t],       v0);
    atomicAdd(&g_v[t + 256], v1);
    atomicAdd(&g_v[t + 512], v2);
    if (t == 0) atomicAdd(&g_diag, dacc);
}

__global__ void __launch_bounds__(THREADS)
final_kernel(float* __restrict__ out, int nrows) {
    __shared__ float red[8];
    const int t    = threadIdx.x;
    const int lane = t & 31;
    const int warp = t >> 5;

    float p = g_u[t]       * g_v[t]
            + g_u[t + 256] * g_v[t + 256]
            + g_u[t + 512] * g_v[t + 512];

    #pragma unroll
    for (int o = 16; o > 0; o >>= 1)
        p += __shfl_down_sync(0xffffffffu, p, o);
    if (lane == 0) red[warp] = p;
    __syncthreads();

    if (t == 0) {
        float uv = 0.f;
        #pragma unroll
        for (int w = 0; w < 8; w++) uv += red[w];
        double n = (double)nrows;
        double loss = n * (n - 1.0) * DELTA_D
                    - n * (double)g_diag
                    + (double)uv;
        out[0] = (float)loss;
    }
}

extern "C" void kernel_launch(void* const* d_in, const int* in_sizes, int n_in,
                              void* d_out, int out_size) {
    const float* X = (const float*)d_in[0];
    const float* Y = (const float*)d_in[1];
    float* out = (float*)d_out;
    int nrows = in_sizes[0] / D_DIM;

    zero_kernel<<<1, THREADS>>>();
    int grid = GRID < nrows ? GRID : nrows;
    stream_kernel<<<grid, THREADS>>>(X, Y, nrows);
    final_kernel<<<1, THREADS>>>(out, nrows);
}